// round 13
// baseline (speedup 1.0000x reference)
#include <cuda_runtime.h>
#include <cstdint>
#include <math.h>

#define THREADS 256
#define ROWS_PER_TILE 484                      // even; 4133 tiles -> 581x7 + 11x6 over 592 blocks
#define OM_TILE_BYTES (ROWS_PER_TILE * 40)     // 19360
#define IF_TILE_BYTES (ROWS_PER_TILE * 4)      // 1936
#define GRID 592                               // 4 blocks / SM on 148 SMs

__device__ double g_acc;             // reset by last block each replay
__device__ unsigned int g_ticket;    // reset by last block each replay

__device__ __forceinline__ unsigned int smem_u32(const void* p) {
    unsigned int a;
    asm("{ .reg .u64 t; cvta.to.shared.u64 t, %1; cvt.u32.u64 %0, t; }"
        : "=r"(a) : "l"(p));
    return a;
}

__global__ void __launch_bounds__(THREADS) fused_kernel(
    const float* __restrict__ para,
    const float* __restrict__ omega,
    const float* __restrict__ infd,
    float* __restrict__ out,
    int nrows, int ntiles)
{
    __shared__ __align__(128) char s_om[2][OM_TILE_BYTES];
    __shared__ __align__(16)  char s_if[2][IF_TILE_BYTES];
    __shared__ __align__(8)   unsigned long long s_bar[2];
    __shared__ float warp_sums[THREADS / 32];
    __shared__ bool s_is_last;

    const int tid = threadIdx.x;

    // ---- scalar constants ----
    float x00 = para[0], x01 = para[1], x10 = para[2], x11 = para[3];
    float av   = 0.5f * (x00 - x11);
    float rez  = 0.5f + 0.5f * (x01 + x10);
    float imz  = 0.5f * (x01 - x10);
    float rsq  = av * av + rez * rez + imz * imz;
    float c    = rez * rez;

    // ---- init barriers ----
    unsigned int bar0 = smem_u32(&s_bar[0]);
    unsigned int bar1 = smem_u32(&s_bar[1]);
    if (tid == 0) {
        asm volatile("mbarrier.init.shared.b64 [%0], 1;" :: "r"(bar0) : "memory");
        asm volatile("mbarrier.init.shared.b64 [%0], 1;" :: "r"(bar1) : "memory");
    }
    __syncthreads();

    const unsigned int bars[2] = {bar0, bar1};
    int ph0 = 0, ph1 = 0;

    // number of tiles this block owns (tile idx = blockIdx.x + k*GRID)
    int K = 0;
    { int b = blockIdx.x; if (b < ntiles) K = (ntiles - b + gridDim.x - 1) / gridDim.x; }

    #define ISSUE_TILE(kk, stage) do {                                          \
        int tIdx_ = blockIdx.x + (kk) * gridDim.x;                              \
        int base_row_ = tIdx_ * ROWS_PER_TILE;                                  \
        int rows_ = min(ROWS_PER_TILE, nrows - base_row_);                      \
        unsigned int omb_ = (unsigned int)rows_ * 40u;                          \
        unsigned int ifb_ = (unsigned int)rows_ * 4u;                           \
        unsigned int dst_om_ = smem_u32(s_om[(stage)]);                         \
        unsigned int dst_if_ = smem_u32(s_if[(stage)]);                         \
        const char* src_om_ = (const char*)omega + (size_t)base_row_ * 40;      \
        const char* src_if_ = (const char*)infd + (size_t)base_row_ * 4;        \
        asm volatile("mbarrier.arrive.expect_tx.shared.b64 _, [%0], %1;"        \
                     :: "r"(bars[(stage)]), "r"(omb_ + ifb_) : "memory");       \
        asm volatile("cp.async.bulk.shared::cluster.global.mbarrier::complete_tx::bytes [%0], [%1], %2, [%3];" \
                     :: "r"(dst_om_), "l"(src_om_), "r"(omb_), "r"(bars[(stage)]) : "memory"); \
        asm volatile("cp.async.bulk.shared::cluster.global.mbarrier::complete_tx::bytes [%0], [%1], %2, [%3];" \
                     :: "r"(dst_if_), "l"(src_if_), "r"(ifb_), "r"(bars[(stage)]) : "memory"); \
    } while (0)

    // prologue: issue tile 0 into stage 0
    if (tid == 0 && K > 0) ISSUE_TILE(0, 0);

    float acc = 0.0f;

    for (int k = 0; k < K; k++) {
        int s = k & 1;

        // issue tile k+1 into the other stage (its previous occupant, tile
        // k-1, was fully consumed before the trailing __syncthreads of iter k-1)
        if (tid == 0 && (k + 1) < K) ISSUE_TILE(k + 1, s ^ 1);

        // wait for tile k
        {
            int ph = s ? ph1 : ph0;
            unsigned int done;
            asm volatile(
                "{\n\t.reg .pred p;\n\t"
                "mbarrier.try_wait.parity.acquire.cta.shared::cta.b64 p, [%1], %2;\n\t"
                "selp.b32 %0, 1, 0, p;\n\t}"
                : "=r"(done) : "r"(bars[s]), "r"(ph) : "memory");
            if (!done) {
                asm volatile(
                    "{\n\t.reg .pred P1;\n\t"
                    "W_%=:\n\t"
                    "mbarrier.try_wait.parity.acquire.cta.shared::cta.b64 P1, [%0], %1, 0x989680;\n\t"
                    "@P1 bra.uni D_%=;\n\t"
                    "bra.uni W_%=;\n\t"
                    "D_%=:\n\t}"
                    :: "r"(bars[s]), "r"(ph) : "memory");
            }
            if (s) ph1 ^= 1; else ph0 ^= 1;
        }

        // compute tile k: thread t handles pair t (rows 2t, 2t+1)
        {
            int tIdx = blockIdx.x + k * gridDim.x;
            int rows = min(ROWS_PER_TILE, nrows - tIdx * ROWS_PER_TILE);
            int npairs_t = rows >> 1;
            if (tid < npairs_t) {
                const float4* q = reinterpret_cast<const float4*>(s_om[s] + tid * 80);
                float4 v0 = q[0]; float4 v1 = q[1]; float4 v2 = q[2];
                float4 v3 = q[3]; float4 v4 = q[4];
                float2 f = reinterpret_cast<const float2*>(s_if[s])[tid];

                float t0 = ((v0.x + v0.y) + (v0.z + v0.w))
                         + ((v1.x + v1.y) + (v1.z + v1.w)) + (v2.x + v2.y);
                float t1 = (v2.z + v2.w)
                         + ((v3.x + v3.y) + (v3.z + v3.w))
                         + ((v4.x + v4.y) + (v4.z + v4.w));

                #define ROW(S, F)  do {                                               \
                    float phi  = 0.1f * (S);                                          \
                    float u    = rsq * (phi * phi);                                   \
                    float poly = fmaf(u, fmaf(u, (1.0f/120.0f), (-1.0f/6.0f)), 1.0f); \
                    float sinc = phi * poly;                                          \
                    float d    = ((F) - 1.0f) + sinc * sinc * c;                      \
                    acc = fmaf(d, d, acc);                                            \
                } while (0)

                ROW(t0, f.x);
                ROW(t1, f.y);
                #undef ROW
            }
        }
        __syncthreads();   // all consumers done with stage s before refill at k+1
    }
    #undef ISSUE_TILE

    // ---- float block reduction ----
    #pragma unroll
    for (int off = 16; off > 0; off >>= 1)
        acc += __shfl_down_sync(0xFFFFFFFFu, acc, off);

    int lane = tid & 31;
    int wid  = tid >> 5;
    if (lane == 0) warp_sums[wid] = acc;
    __syncthreads();

    if (wid == 0) {
        float v = (lane < (THREADS / 32)) ? warp_sums[lane] : 0.0f;
        #pragma unroll
        for (int off = 4; off > 0; off >>= 1)
            v += __shfl_down_sync(0xFFFFFFFFu, v, off);
        if (lane == 0) {
            asm volatile("red.release.gpu.global.add.f64 [%0], %1;"
                         :: "l"(&g_acc), "d"((double)v) : "memory");
            unsigned int tk;
            asm volatile("atom.acq_rel.gpu.global.add.u32 %0, [%1], %2;"
                         : "=r"(tk) : "l"(&g_ticket), "r"(1u) : "memory");
            s_is_last = (tk == gridDim.x - 1);
        }
    }
    __syncthreads();

    if (s_is_last && tid == 0) {
        double total;
        asm volatile("atom.acq_rel.gpu.global.add.f64 %0, [%1], %2;"
                     : "=d"(total) : "l"(&g_acc), "d"(0.0) : "memory");
        out[0] = (float)(total / (double)nrows);
        g_acc = 0.0;
        g_ticket = 0u;
    }
}

extern "C" void kernel_launch(void* const* d_in, const int* in_sizes, int n_in,
                              void* d_out, int out_size) {
    const float* para  = (const float*)d_in[0];
    const float* omega = (const float*)d_in[1];
    const float* infd  = (const float*)d_in[2];
    float* out = (float*)d_out;

    int nrows  = in_sizes[2];                                   // 2,000,000
    int ntiles = (nrows + ROWS_PER_TILE - 1) / ROWS_PER_TILE;   // 4133

    int grid = GRID;
    if (grid > ntiles) grid = ntiles;
    fused_kernel<<<grid, THREADS>>>(para, omega, infd, out, nrows, ntiles);
}

// round 14
// speedup vs baseline: 1.3825x; 1.3825x over previous
#include <cuda_runtime.h>
#include <cstdint>
#include <math.h>

#define THREADS 256
#define ROWS_PER_TILE 512                      // 256 pairs per tile
#define OM_TILE_BYTES (ROWS_PER_TILE * 40)     // 20480
#define IF_TILE_BYTES (ROWS_PER_TILE * 4)      // 2048
#define GRID 592                               // 4 blocks / SM on 148 SMs

__device__ double g_acc;             // reset by last block each replay
__device__ unsigned int g_ticket;    // reset by last block each replay

__device__ __forceinline__ unsigned int smem_u32(const void* p) {
    unsigned int a;
    asm("{ .reg .u64 t; cvta.to.shared.u64 t, %1; cvt.u32.u64 %0, t; }"
        : "=r"(a) : "l"(p));
    return a;
}

__global__ void __launch_bounds__(THREADS) fused_kernel(
    const float* __restrict__ para,
    const float* __restrict__ omega,
    const float* __restrict__ infd,
    float* __restrict__ out,
    int nrows, int ntiles)
{
    __shared__ __align__(128) char s_om[2][OM_TILE_BYTES];
    __shared__ __align__(16)  char s_if[2][IF_TILE_BYTES];
    __shared__ __align__(8)   unsigned long long s_bar[2];
    __shared__ float warp_sums[THREADS / 32];
    __shared__ bool s_is_last;

    const int tid = threadIdx.x;

    // ---- scalar constants ----
    float x00 = para[0], x01 = para[1], x10 = para[2], x11 = para[3];
    float av   = 0.5f * (x00 - x11);
    float rez  = 0.5f + 0.5f * (x01 + x10);
    float imz  = 0.5f * (x01 - x10);
    float rsq  = av * av + rez * rez + imz * imz;
    float c    = rez * rez;

    // ---- init barriers ----
    unsigned int bar0 = smem_u32(&s_bar[0]);
    unsigned int bar1 = smem_u32(&s_bar[1]);
    if (tid == 0) {
        asm volatile("mbarrier.init.shared.b64 [%0], 1;" :: "r"(bar0) : "memory");
        asm volatile("mbarrier.init.shared.b64 [%0], 1;" :: "r"(bar1) : "memory");
    }
    __syncthreads();

    const unsigned int bars[2] = {bar0, bar1};
    int ph0 = 0, ph1 = 0;

    // number of tiles this block owns (tile idx = blockIdx.x + k*GRID)
    int K = 0;
    { int b = blockIdx.x; if (b < ntiles) K = (ntiles - b + gridDim.x - 1) / gridDim.x; }

    #define ISSUE_TILE(kk, stage) do {                                          \
        int tIdx_ = blockIdx.x + (kk) * gridDim.x;                              \
        int base_row_ = tIdx_ * ROWS_PER_TILE;                                  \
        int rows_ = min(ROWS_PER_TILE, nrows - base_row_);                      \
        unsigned int omb_ = (unsigned int)rows_ * 40u;                          \
        unsigned int ifb_ = (unsigned int)rows_ * 4u;                           \
        unsigned int dst_om_ = smem_u32(s_om[(stage)]);                         \
        unsigned int dst_if_ = smem_u32(s_if[(stage)]);                         \
        const char* src_om_ = (const char*)omega + (size_t)base_row_ * 40;      \
        const char* src_if_ = (const char*)infd + (size_t)base_row_ * 4;        \
        asm volatile("mbarrier.arrive.expect_tx.shared.b64 _, [%0], %1;"        \
                     :: "r"(bars[(stage)]), "r"(omb_ + ifb_) : "memory");       \
        asm volatile("cp.async.bulk.shared::cluster.global.mbarrier::complete_tx::bytes [%0], [%1], %2, [%3];" \
                     :: "r"(dst_om_), "l"(src_om_), "r"(omb_), "r"(bars[(stage)]) : "memory"); \
        asm volatile("cp.async.bulk.shared::cluster.global.mbarrier::complete_tx::bytes [%0], [%1], %2, [%3];" \
                     :: "r"(dst_if_), "l"(src_if_), "r"(ifb_), "r"(bars[(stage)]) : "memory"); \
    } while (0)

    // prologue: issue tile 0 into stage 0
    if (tid == 0 && K > 0) ISSUE_TILE(0, 0);

    float acc = 0.0f;

    for (int k = 0; k < K; k++) {
        int s = k & 1;

        // issue tile k+1 into the other stage (its previous occupant, tile
        // k-1, was fully consumed before the trailing __syncthreads of iter k-1)
        if (tid == 0 && (k + 1) < K) ISSUE_TILE(k + 1, s ^ 1);

        // wait for tile k
        {
            int ph = s ? ph1 : ph0;
            unsigned int done;
            asm volatile(
                "{\n\t.reg .pred p;\n\t"
                "mbarrier.try_wait.parity.acquire.cta.shared::cta.b64 p, [%1], %2;\n\t"
                "selp.b32 %0, 1, 0, p;\n\t}"
                : "=r"(done) : "r"(bars[s]), "r"(ph) : "memory");
            if (!done) {
                asm volatile(
                    "{\n\t.reg .pred P1;\n\t"
                    "W_%=:\n\t"
                    "mbarrier.try_wait.parity.acquire.cta.shared::cta.b64 P1, [%0], %1, 0x989680;\n\t"
                    "@P1 bra.uni D_%=;\n\t"
                    "bra.uni W_%=;\n\t"
                    "D_%=:\n\t}"
                    :: "r"(bars[s]), "r"(ph) : "memory");
            }
            if (s) ph1 ^= 1; else ph0 ^= 1;
        }

        // compute tile k: thread t handles pair t (rows 2t, 2t+1)
        {
            int tIdx = blockIdx.x + k * gridDim.x;
            int rows = min(ROWS_PER_TILE, nrows - tIdx * ROWS_PER_TILE);
            int npairs_t = rows >> 1;
            if (tid < npairs_t) {
                const float4* q = reinterpret_cast<const float4*>(s_om[s] + tid * 80);
                float4 v0 = q[0]; float4 v1 = q[1]; float4 v2 = q[2];
                float4 v3 = q[3]; float4 v4 = q[4];
                float2 f = reinterpret_cast<const float2*>(s_if[s])[tid];

                float t0 = ((v0.x + v0.y) + (v0.z + v0.w))
                         + ((v1.x + v1.y) + (v1.z + v1.w)) + (v2.x + v2.y);
                float t1 = (v2.z + v2.w)
                         + ((v3.x + v3.y) + (v3.z + v3.w))
                         + ((v4.x + v4.y) + (v4.z + v4.w));

                #define ROW(S, F)  do {                                               \
                    float phi  = 0.1f * (S);                                          \
                    float u    = rsq * (phi * phi);                                   \
                    float poly = fmaf(u, fmaf(u, (1.0f/120.0f), (-1.0f/6.0f)), 1.0f); \
                    float sinc = phi * poly;                                          \
                    float d    = ((F) - 1.0f) + sinc * sinc * c;                      \
                    acc = fmaf(d, d, acc);                                            \
                } while (0)

                ROW(t0, f.x);
                ROW(t1, f.y);
                #undef ROW
            }
        }
        __syncthreads();   // all consumers done with stage s before refill at k+1
    }
    #undef ISSUE_TILE

    // ---- float block reduction ----
    #pragma unroll
    for (int off = 16; off > 0; off >>= 1)
        acc += __shfl_down_sync(0xFFFFFFFFu, acc, off);

    int lane = tid & 31;
    int wid  = tid >> 5;
    if (lane == 0) warp_sums[wid] = acc;
    __syncthreads();

    if (wid == 0) {
        float v = (lane < (THREADS / 32)) ? warp_sums[lane] : 0.0f;
        #pragma unroll
        for (int off = 4; off > 0; off >>= 1)
            v += __shfl_down_sync(0xFFFFFFFFu, v, off);
        if (lane == 0) {
            asm volatile("red.release.gpu.global.add.f64 [%0], %1;"
                         :: "l"(&g_acc), "d"((double)v) : "memory");
            unsigned int tk;
            asm volatile("atom.acq_rel.gpu.global.add.u32 %0, [%1], %2;"
                         : "=r"(tk) : "l"(&g_ticket), "r"(1u) : "memory");
            s_is_last = (tk == gridDim.x - 1);
        }
    }
    __syncthreads();

    if (s_is_last && tid == 0) {
        double total;
        asm volatile("atom.acq_rel.gpu.global.add.f64 %0, [%1], %2;"
                     : "=d"(total) : "l"(&g_acc), "d"(0.0) : "memory");
        out[0] = (float)(total / (double)nrows);
        g_acc = 0.0;
        g_ticket = 0u;
    }
}

extern "C" void kernel_launch(void* const* d_in, const int* in_sizes, int n_in,
                              void* d_out, int out_size) {
    const float* para  = (const float*)d_in[0];
    const float* omega = (const float*)d_in[1];
    const float* infd  = (const float*)d_in[2];
    float* out = (float*)d_out;

    int nrows  = in_sizes[2];                                   // 2,000,000
    int ntiles = (nrows + ROWS_PER_TILE - 1) / ROWS_PER_TILE;   // 3907

    int grid = GRID;
    if (grid > ntiles) grid = ntiles;
    fused_kernel<<<grid, THREADS>>>(para, omega, infd, out, nrows, ntiles);
}